// round 6
// baseline (speedup 1.0000x reference)
#include <cuda_runtime.h>
#include <cstdint>

// EmbeddingBagCollection: T=8 tables [V=100000, D=128] fp32, indices [T,B=4096,L=50] int32.
// out[b, t*D + d] = sum_{l} tables[t, indices[t,b,l], d]
//
// One warp per bag; lane owns float4 of the row. Table-major bag order.
// Indices staged in smem (no global idx dependency in the gather loop).
// 6 CTAs/SM (regs<=42, CHUNK=5): 48 warps/SM deepens the HBM request queue
// -> higher achieved DRAM bandwidth on random 512B gathers.
// Wave working set ~1.7 tables ~ 89 MB < L2 126 MB -> compulsory traffic only.

#define T_TABLES 8
#define B_BATCH  4096
#define L_BAG    50
#define V_VOCAB  100000
#define D_DIM    128
#define CHUNK    5
#define WARPS_PER_BLOCK 8

__global__ void __launch_bounds__(256, 6)
ebc_kernel(const int*   __restrict__ indices,
           const float* __restrict__ tables,
           float*       __restrict__ out)
{
    __shared__ int s_idx[WARPS_PER_BLOCK * L_BAG];   // 400 ints = 1600 B

    const int tid     = threadIdx.x;
    const int warp_id = blockIdx.x * WARPS_PER_BLOCK + (tid >> 5);
    const int lane    = tid & 31;

    // Stage this block's indices: 400 consecutive ints, coalesced.
    {
        const int* __restrict__ g = indices + (size_t)blockIdx.x * WARPS_PER_BLOCK * L_BAG;
        #pragma unroll
        for (int i = tid; i < WARPS_PER_BLOCK * L_BAG; i += 256)
            s_idx[i] = g[i];
    }
    __syncthreads();

    const int t = warp_id / B_BATCH;   // table id
    const int b = warp_id % B_BATCH;   // bag id

    const int*   bag = s_idx + (tid >> 5) * L_BAG;
    const float* __restrict__ tab = tables + (size_t)t * V_VOCAB * D_DIM
                                           + (size_t)lane * 4;

    float4 acc = make_float4(0.f, 0.f, 0.f, 0.f);

    #pragma unroll
    for (int base = 0; base < L_BAG; base += CHUNK) {
        float4 v[CHUNK];
        #pragma unroll
        for (int j = 0; j < CHUNK; ++j) {
            const int r = bag[base + j];               // LDS, cheap
            v[j] = *reinterpret_cast<const float4*>(tab + (size_t)r * D_DIM);
        }
        #pragma unroll
        for (int j = 0; j < CHUNK; ++j) {
            acc.x += v[j].x;
            acc.y += v[j].y;
            acc.z += v[j].z;
            acc.w += v[j].w;
        }
    }

    float4* __restrict__ dst = reinterpret_cast<float4*>(
        out + (size_t)b * (T_TABLES * D_DIM) + t * D_DIM + lane * 4);
    *dst = acc;
}

extern "C" void kernel_launch(void* const* d_in, const int* in_sizes, int n_in,
                              void* d_out, int out_size)
{
    const long long N_IDX = (long long)T_TABLES * B_BATCH * L_BAG;

    const int*   indices;
    const float* tables;
    if ((long long)in_sizes[0] == N_IDX) {
        indices = (const int*)d_in[0];
        tables  = (const float*)d_in[1];
    } else {
        indices = (const int*)d_in[1];
        tables  = (const float*)d_in[0];
    }
    float* out = (float*)d_out;

    const int total_warps = T_TABLES * B_BATCH;              // 32768 bags
    const int blocks      = total_warps / WARPS_PER_BLOCK;   // 4096 blocks

    ebc_kernel<<<blocks, 256>>>(indices, tables, out);
}

// round 7
// speedup vs baseline: 1.0288x; 1.0288x over previous
#include <cuda_runtime.h>
#include <cstdint>

// EmbeddingBagCollection: T=8 tables [V=100000, D=128] fp32, indices [T,B=4096,L=50] int32.
// out[b, t*D + d] = sum_{l} tables[t, indices[t,b,l], d]
//
// R4 config (best: 4 CTAs/SM, CHUNK=10, smem-staged idx) plus cache policy:
//  - row gathers:  ld.global.cg (L2 only; L1 allocation is useless here)
//  - output store: st.global.cs (streaming; don't evict live table rows from L2)

#define T_TABLES 8
#define B_BATCH  4096
#define L_BAG    50
#define V_VOCAB  100000
#define D_DIM    128
#define CHUNK    10
#define WARPS_PER_BLOCK 8

__device__ __forceinline__ float4 ldg_cg_f4(const float* p) {
    float4 v;
    asm volatile("ld.global.cg.v4.f32 {%0,%1,%2,%3}, [%4];"
                 : "=f"(v.x), "=f"(v.y), "=f"(v.z), "=f"(v.w)
                 : "l"(p));
    return v;
}

__device__ __forceinline__ void stg_cs_f4(float* p, float4 v) {
    asm volatile("st.global.cs.v4.f32 [%0], {%1,%2,%3,%4};"
                 :: "l"(p), "f"(v.x), "f"(v.y), "f"(v.z), "f"(v.w)
                 : "memory");
}

__global__ void __launch_bounds__(256, 4)
ebc_kernel(const int*   __restrict__ indices,
           const float* __restrict__ tables,
           float*       __restrict__ out)
{
    __shared__ int s_idx[WARPS_PER_BLOCK * L_BAG];   // 400 ints = 1600 B

    const int tid     = threadIdx.x;
    const int warp_id = blockIdx.x * WARPS_PER_BLOCK + (tid >> 5);
    const int lane    = tid & 31;

    // Stage this block's indices: 400 consecutive ints, coalesced.
    {
        const int* __restrict__ g = indices + (size_t)blockIdx.x * WARPS_PER_BLOCK * L_BAG;
        #pragma unroll
        for (int i = tid; i < WARPS_PER_BLOCK * L_BAG; i += 256)
            s_idx[i] = g[i];
    }
    __syncthreads();

    const int t = warp_id / B_BATCH;   // table id
    const int b = warp_id % B_BATCH;   // bag id

    const int*   bag = s_idx + (tid >> 5) * L_BAG;
    const float* __restrict__ tab = tables + (size_t)t * V_VOCAB * D_DIM
                                           + (size_t)lane * 4;

    float4 acc = make_float4(0.f, 0.f, 0.f, 0.f);

    #pragma unroll
    for (int base = 0; base < L_BAG; base += CHUNK) {
        float4 v[CHUNK];
        #pragma unroll
        for (int j = 0; j < CHUNK; ++j) {
            const int r = bag[base + j];               // LDS, cheap
            v[j] = ldg_cg_f4(tab + (size_t)r * D_DIM); // L2-only gather
        }
        #pragma unroll
        for (int j = 0; j < CHUNK; ++j) {
            acc.x += v[j].x;
            acc.y += v[j].y;
            acc.z += v[j].z;
            acc.w += v[j].w;
        }
    }

    stg_cs_f4(out + (size_t)b * (T_TABLES * D_DIM) + t * D_DIM + lane * 4, acc);
}

extern "C" void kernel_launch(void* const* d_in, const int* in_sizes, int n_in,
                              void* d_out, int out_size)
{
    const long long N_IDX = (long long)T_TABLES * B_BATCH * L_BAG;

    const int*   indices;
    const float* tables;
    if ((long long)in_sizes[0] == N_IDX) {
        indices = (const int*)d_in[0];
        tables  = (const float*)d_in[1];
    } else {
        indices = (const int*)d_in[1];
        tables  = (const float*)d_in[0];
    }
    float* out = (float*)d_out;

    const int total_warps = T_TABLES * B_BATCH;              // 32768 bags
    const int blocks      = total_warps / WARPS_PER_BLOCK;   // 4096 blocks

    ebc_kernel<<<blocks, 256>>>(indices, tables, out);
}